// round 10
// baseline (speedup 1.0000x reference)
#include <cuda_runtime.h>
#include <cuda_bf16.h>
#include <cuda_fp16.h>
#include <math.h>
#include <stdint.h>

#define NTOK 2048
#define DMOD 512
#define NH 8
#define HDIM 64
#define NBINS 16

// ---------------------------------------------------------------------------
// Scratch (no cudaMalloc). Only referenced from DEVICE code.
// ---------------------------------------------------------------------------
__device__ float g_Vc[NTOK * DMOD];                              // V proj (fp32, compact)
__device__ __nv_bfloat16 g_Xh[NTOK * DMOD], g_Xl[NTOK * DMOD];   // split x
__device__ __nv_bfloat16 g_Wth[1536 * 512], g_Wtl[1536 * 512];   // (Wq|Wk|Wv)^T split
__device__ __nv_bfloat16 g_Woth[512 * 512], g_Wotl[512 * 512];   // Wo^T split
__device__ __nv_bfloat16 g_AOh[NTOK * DMOD], g_AOl[NTOK * DMOD]; // attn out split
__device__ __half g_Qf[NTOK * DMOD];                             // [h][tok][64] fp16
__device__ __half g_Kf[NTOK * DMOD];                             // [h][tok][64] fp16
__device__ __half g_Vtf[NTOK * DMOD];                            // [h][d][2048] fp16
__device__ uint8_t g_bins[NTOK * NTOK];

#define LOG2E 1.4426950408889634f

// ---------------------------------------------------------------------------
// mma.sync / cp.async / ldmatrix helpers
// ---------------------------------------------------------------------------
__device__ __forceinline__ void mma_bf16(float* c, const uint32_t* a,
                                         uint32_t b0, uint32_t b1) {
    asm volatile(
        "mma.sync.aligned.m16n8k16.row.col.f32.bf16.bf16.f32 "
        "{%0,%1,%2,%3},{%4,%5,%6,%7},{%8,%9},{%0,%1,%2,%3};"
        : "+f"(c[0]), "+f"(c[1]), "+f"(c[2]), "+f"(c[3])
        : "r"(a[0]), "r"(a[1]), "r"(a[2]), "r"(a[3]), "r"(b0), "r"(b1));
}
__device__ __forceinline__ void mma_fp16(float* c, const uint32_t* a,
                                         uint32_t b0, uint32_t b1) {
    asm volatile(
        "mma.sync.aligned.m16n8k16.row.col.f32.f16.f16.f32 "
        "{%0,%1,%2,%3},{%4,%5,%6,%7},{%8,%9},{%0,%1,%2,%3};"
        : "+f"(c[0]), "+f"(c[1]), "+f"(c[2]), "+f"(c[3])
        : "r"(a[0]), "r"(a[1]), "r"(a[2]), "r"(a[3]), "r"(b0), "r"(b1));
}
__device__ __forceinline__ void ldsm4(uint32_t& r0, uint32_t& r1,
                                      uint32_t& r2, uint32_t& r3, uint32_t addr) {
    asm volatile("ldmatrix.sync.aligned.m8n8.x4.shared.b16 {%0,%1,%2,%3}, [%4];"
                 : "=r"(r0), "=r"(r1), "=r"(r2), "=r"(r3) : "r"(addr));
}
__device__ __forceinline__ void cp16(uint32_t dst, const void* src) {
    asm volatile("cp.async.cg.shared.global [%0], [%1], 16;" :: "r"(dst), "l"(src));
}
__device__ __forceinline__ uint32_t smem_u32(const void* p) {
    uint32_t a;
    asm("{ .reg .u64 t; cvta.to.shared.u64 t, %1; cvt.u32.u64 %0, t; }"
        : "=r"(a) : "l"(p));
    return a;
}
__device__ __forceinline__ uint32_t pack2bf(float a, float b) {
    __nv_bfloat162 t;
    t.x = __float2bfloat16_rn(a);
    t.y = __float2bfloat16_rn(b);
    return *(uint32_t*)&t;
}
__device__ __forceinline__ uint32_t pack2h(float a, float b) {
    __half2 t;
    t.x = __float2half_rn(a);
    t.y = __float2half_rn(b);
    return *(uint32_t*)&t;
}
__device__ __forceinline__ float fast_exp2(float x) {
    float r;
    asm("ex2.approx.ftz.f32 %0, %1;" : "=f"(r) : "f"(x));
    return r;
}

// ---------------------------------------------------------------------------
// Split-bf16 tensor-core GEMM (validated R9), ldmatrix operand loads.
// mode 0: QKV projection, epilogue -> g_Qf / g_Kf (fp16), g_Vc (fp32).
// mode 1: out projection -> C_ext fp32.
// ---------------------------------------------------------------------------
#define GPIT 80
#define GAH 0
#define GAL 10240
#define GBH 20480
#define GBL 30720
#define GSTAGE 40960
#define GEMM_SMEM (2 * GSTAGE)

__global__ __launch_bounds__(256, 2) void gemm_mma_kernel(
    int mode, const float* __restrict__ b0p, const float* __restrict__ b1p,
    const float* __restrict__ b2p, float* __restrict__ C_ext)
{
    extern __shared__ char smem[];
    const __nv_bfloat16 *Ah, *Al, *Bth, *Btl;
    if (mode == 0) {
        Ah = g_Xh;  Al = g_Xl;  Bth = g_Wth;  Btl = g_Wtl;
    } else {
        Ah = g_AOh; Al = g_AOl; Bth = g_Woth; Btl = g_Wotl;
    }

    const int tid = threadIdx.x;
    const int w = tid >> 5, l = tid & 31, g = l >> 2, t = l & 3;
    const int q4 = l >> 3, r8 = l & 7;
    const int n0 = blockIdx.x * 128;
    const int mb = blockIdx.y * 128;
    const uint32_t sbase = smem_u32(smem);

    const uint32_t aln = (uint32_t)(w * 16 + 8 * (q4 & 1) + r8) * GPIT + 16 * (q4 >> 1);
    const uint32_t bln = (uint32_t)(8 * (q4 >> 1) + r8) * GPIT + 16 * (q4 & 1);

    auto load = [&](int kc, int st) {
        uint32_t b = sbase + st * GSTAGE;
        #pragma unroll
        for (int p = 0; p < 2; p++) {
            int i = tid + p * 256;
            int r = i >> 2, c = i & 3;
            uint32_t so = r * GPIT + c * 16;
            size_t ga = ((size_t)(mb + r) * 512 + kc * 32) * 2 + c * 16;
            cp16(b + GAH + so, (const char*)Ah + ga);
            cp16(b + GAL + so, (const char*)Al + ga);
            size_t gb = ((size_t)(n0 + r) * 512 + kc * 32) * 2 + c * 16;
            cp16(b + GBH + so, (const char*)Bth + gb);
            cp16(b + GBL + so, (const char*)Btl + gb);
        }
        asm volatile("cp.async.commit_group;" ::: "memory");
    };

    float acc[16][4];
    #pragma unroll
    for (int j = 0; j < 16; j++)
        #pragma unroll
        for (int i = 0; i < 4; i++) acc[j][i] = 0.0f;

    load(0, 0);
    for (int kc = 0; kc < 16; kc++) {
        if (kc + 1 < 16) {
            load(kc + 1, (kc + 1) & 1);
            asm volatile("cp.async.wait_group 1;" ::: "memory");
        } else {
            asm volatile("cp.async.wait_group 0;" ::: "memory");
        }
        __syncthreads();
        const uint32_t sb = sbase + (kc & 1) * GSTAGE;

        #pragma unroll
        for (int kk = 0; kk < 2; kk++) {
            uint32_t ah[4], al[4];
            ldsm4(ah[0], ah[1], ah[2], ah[3], sb + GAH + aln + kk * 32);
            ldsm4(al[0], al[1], al[2], al[3], sb + GAL + aln + kk * 32);
            #pragma unroll
            for (int jp = 0; jp < 8; jp++) {
                uint32_t bh0, bh1, bh2, bh3, bl0, bl1, bl2, bl3;
                uint32_t ba = bln + (uint32_t)jp * (16 * GPIT) + kk * 32;
                ldsm4(bh0, bh1, bh2, bh3, sb + GBH + ba);
                ldsm4(bl0, bl1, bl2, bl3, sb + GBL + ba);
                mma_bf16(acc[2 * jp],     ah, bh0, bh1);
                mma_bf16(acc[2 * jp],     al, bh0, bh1);
                mma_bf16(acc[2 * jp],     ah, bl0, bl1);
                mma_bf16(acc[2 * jp + 1], ah, bh2, bh3);
                mma_bf16(acc[2 * jp + 1], al, bh2, bh3);
                mma_bf16(acc[2 * jp + 1], ah, bl2, bl3);
            }
        }
        __syncthreads();
    }

    const int r0 = mb + w * 16 + g, r1 = r0 + 8;
    if (mode == 1) {
        #pragma unroll
        for (int j = 0; j < 16; j++) {
            int col = n0 + 8 * j + 2 * t;
            float bv0 = b0p[col], bv1 = b0p[col + 1];
            *(float2*)&C_ext[(size_t)r0 * 512 + col] =
                make_float2(acc[j][0] + bv0, acc[j][1] + bv1);
            *(float2*)&C_ext[(size_t)r1 * 512 + col] =
                make_float2(acc[j][2] + bv0, acc[j][3] + bv1);
        }
    } else {
        const float QS = 0.125f * LOG2E;
        #pragma unroll
        for (int j = 0; j < 16; j++) {
            int col = n0 + 8 * j + 2 * t;
            const float* bp = (col < 512) ? b0p : (col < 1024 ? b1p : b2p);
            int cc = col & 511;
            float bv0 = bp[cc], bv1 = bp[cc + 1];
            float v00 = acc[j][0] + bv0, v01 = acc[j][1] + bv1;
            float v10 = acc[j][2] + bv0, v11 = acc[j][3] + bv1;
            if (col < 512) {
                int h = cc >> 6, d = cc & 63;
                *(uint32_t*)&g_Qf[((size_t)h * NTOK + r0) * HDIM + d] =
                    pack2h(v00 * QS, v01 * QS);
                *(uint32_t*)&g_Qf[((size_t)h * NTOK + r1) * HDIM + d] =
                    pack2h(v10 * QS, v11 * QS);
            } else if (col < 1024) {
                int h = cc >> 6, d = cc & 63;
                *(uint32_t*)&g_Kf[((size_t)h * NTOK + r0) * HDIM + d] = pack2h(v00, v01);
                *(uint32_t*)&g_Kf[((size_t)h * NTOK + r1) * HDIM + d] = pack2h(v10, v11);
            } else {
                *(float2*)&g_Vc[(size_t)r0 * 512 + cc] = make_float2(v00, v01);
                *(float2*)&g_Vc[(size_t)r1 * 512 + cc] = make_float2(v10, v11);
            }
        }
    }
}

// ---------------------------------------------------------------------------
// Fused input prep:
//   blocks [0,4096): z bins  |  [4096,5120): W transpose+split  |  [5120,9216): x split
// ---------------------------------------------------------------------------
__device__ __forceinline__ uint8_t bin_of(float z) {
    int b = (int)floorf(z / 5.0f * 16.0f);
    return (uint8_t)max(0, min(NBINS - 1, b));
}

__global__ __launch_bounds__(256) void prep_in_kernel(
    const float* __restrict__ x, const float* __restrict__ zmat,
    const float* __restrict__ Wq, const float* __restrict__ Wk,
    const float* __restrict__ Wv, const float* __restrict__ Wo)
{
    int bx = blockIdx.x;
    int tid = threadIdx.x;
    if (bx < 4096) {
        size_t i = (size_t)bx * 256 + tid;
        float4 z = *(const float4*)(zmat + i * 4);
        uchar4 b;
        b.x = bin_of(z.x); b.y = bin_of(z.y); b.z = bin_of(z.z); b.w = bin_of(z.w);
        *(uchar4*)(g_bins + i * 4) = b;
    } else if (bx < 5120) {
        __shared__ float ts[32][33];
        int bb = bx - 4096;
        int zb = bb >> 8, rem = bb & 255;
        int k0 = (rem & 15) * 32;
        int n0 = (rem >> 4) * 32;
        const float* src;
        __nv_bfloat16 *dh, *dl;
        int nbase;
        if (zb == 0)      { src = Wq; dh = g_Wth;  dl = g_Wtl;  nbase = 0; }
        else if (zb == 1) { src = Wk; dh = g_Wth;  dl = g_Wtl;  nbase = 512; }
        else if (zb == 2) { src = Wv; dh = g_Wth;  dl = g_Wtl;  nbase = 1024; }
        else              { src = Wo; dh = g_Woth; dl = g_Wotl; nbase = 0; }
        int tx = tid & 31, ty = tid >> 5;
        #pragma unroll
        for (int i = 0; i < 4; i++) {
            int r = ty + i * 8;
            ts[r][tx] = src[(size_t)(k0 + r) * 512 + n0 + tx];
        }
        __syncthreads();
        #pragma unroll
        for (int i = 0; i < 4; i++) {
            int nn = ty + i * 8;
            float v = ts[tx][nn];
            __nv_bfloat16 h = __float2bfloat16_rn(v);
            size_t dst = (size_t)(nbase + n0 + nn) * 512 + k0 + tx;
            dh[dst] = h;
            dl[dst] = __float2bfloat16_rn(v - __bfloat162float(h));
        }
    } else {
        int i = (bx - 5120) * 256 + tid;
        float v = x[i];
        __nv_bfloat16 h = __float2bfloat16_rn(v);
        g_Xh[i] = h;
        g_Xl[i] = __float2bfloat16_rn(v - __bfloat162float(h));
    }
}

// ---------------------------------------------------------------------------
// V transpose: g_Vc [tok][512] fp32 -> g_Vtf [h][d][2048] fp16
// ---------------------------------------------------------------------------
__global__ __launch_bounds__(256) void prep_vt_kernel()
{
    __shared__ float ts[32][33];
    int bx = blockIdx.x;
    int tok0 = (bx & 63) * 32;
    int c0   = (bx >> 6) * 32;
    int tid = threadIdx.x;
    int tx = tid & 31, ty = tid >> 5;
    #pragma unroll
    for (int i = 0; i < 4; i++) {
        int r = ty + i * 8;
        ts[r][tx] = g_Vc[(size_t)(tok0 + r) * 512 + c0 + tx];
    }
    __syncthreads();
    #pragma unroll
    for (int i = 0; i < 4; i++) {
        int dd = ty + i * 8;
        int col = c0 + dd, h = col >> 6, hd = col & 63;
        g_Vtf[((size_t)h * HDIM + hd) * NTOK + tok0 + tx] = __float2half_rn(ts[tx][dd]);
    }
}

// ---------------------------------------------------------------------------
// fp16 mma.sync flash attention, key-split warps + interleaved pipeline.
// CTA: 64 q-rows, 8 warps. Warps 0-3: keys [0,64) of each tile; warps 4-7:
// keys [64,128). Grid (32, 8) = 256 CTAs -> 2 CTAs/SM (16 warps/SM).
// Per k16-slice: S-MMAs -> exp/pack -> l,O-MMAs (short chains, low regs).
// Cross-warp O/l reduction via smem at the end.
// ---------------------------------------------------------------------------
#define KP 144
#define VP 272
#define BP 144
#define KF_O 0
#define VT_O 18432
#define BN_O 35840
#define STAGE 45056
#define ATTN_SMEM (2 * STAGE)

__global__ __launch_bounds__(256, 2) void attn_mma_kernel(const float* __restrict__ ztab)
{
    extern __shared__ char smem[];
    __shared__ float zt[NBINS];

    const int tid = threadIdx.x;
    const int w   = tid >> 5;        // 0..7
    const int wq  = w & 3;           // row-group
    const int hf  = w >> 2;          // key-half
    const int ko  = hf * 64;         // key offset in tile
    const int l   = tid & 31;
    const int g   = l >> 2;
    const int t   = l & 3;
    const int q4  = l >> 3, r8 = l & 7;
    const int h   = blockIdx.y;
    const int q0  = blockIdx.x * 64;
    const int m0  = wq * 16;
    const uint32_t ONES2 = 0x3C003C00u;

    if (tid < NBINS) zt[tid] = ztab[tid * NH + h] * LOG2E;

    const uint32_t sbase = smem_u32(smem);

    const uint32_t kln = (uint32_t)(ko + 8 * (q4 >> 1) + r8) * KP + 16 * (q4 & 1);
    const uint32_t vln = (uint32_t)(8 * (q4 >> 1) + r8) * VP + 16 * (q4 & 1) + (uint32_t)ko * 2;

    auto load_tile = [&](int kt, int stage) {
        uint32_t base = sbase + stage * STAGE;
        #pragma unroll
        for (int p = 0; p < 4; p++) {             // K: 128 rows x 128B
            int i = tid + p * 256;
            int r = i >> 3, c = i & 7;
            cp16(base + KF_O + r * KP + c * 16,
                 (const char*)g_Kf + (((size_t)h * NTOK + kt * 128 + r) * HDIM) * 2 + c * 16);
        }
        #pragma unroll
        for (int p = 0; p < 4; p++) {             // Vt: 64 rows x 256B
            int i = tid + p * 256;
            int d = i >> 4, c = i & 15;
            cp16(base + VT_O + d * VP + c * 16,
                 (const char*)g_Vtf + (((size_t)h * HDIM + d) * NTOK + kt * 128) * 2 + c * 16);
        }
        #pragma unroll
        for (int p = 0; p < 2; p++) {             // bins: 64 rows x 128B
            int i = tid + p * 256;
            int r = i >> 3, c = i & 7;
            cp16(base + BN_O + r * BP + c * 16,
                 g_bins + (size_t)(q0 + r) * NTOK + kt * 128 + c * 16);
        }
        asm volatile("cp.async.commit_group;" ::: "memory");
    };

    load_tile(0, 0);

    uint32_t qf[4][4];
    {
        const uint16_t* qb = (const uint16_t*)g_Qf + ((size_t)h * NTOK + q0 + m0) * HDIM;
        #pragma unroll
        for (int kk = 0; kk < 4; kk++) {
            int c0 = 16 * kk + 2 * t;
            qf[kk][0] = *(const uint32_t*)(qb + (size_t)g * HDIM + c0);
            qf[kk][1] = *(const uint32_t*)(qb + (size_t)(g + 8) * HDIM + c0);
            qf[kk][2] = *(const uint32_t*)(qb + (size_t)g * HDIM + c0 + 8);
            qf[kk][3] = *(const uint32_t*)(qb + (size_t)(g + 8) * HDIM + c0 + 8);
        }
    }

    float oc[8][4];
    #pragma unroll
    for (int j = 0; j < 8; j++)
        #pragma unroll
        for (int i = 0; i < 4; i++) oc[j][i] = 0.0f;
    float lc[4] = {0.0f, 0.0f, 0.0f, 0.0f};

    for (int kt = 0; kt < NTOK / 128; kt++) {
        if (kt + 1 < NTOK / 128) {
            load_tile(kt + 1, (kt + 1) & 1);
            asm volatile("cp.async.wait_group 1;" ::: "memory");
        } else {
            asm volatile("cp.async.wait_group 0;" ::: "memory");
        }
        __syncthreads();

        const uint32_t sb = sbase + (kt & 1) * STAGE;
        const char* BN = smem + (kt & 1) * STAGE + BN_O;

        // 4 k16-slices of this warp's 64 keys: S -> softmax -> l,O per slice
        #pragma unroll
        for (int kp = 0; kp < 4; kp++) {
            float sc0[4] = {0.f, 0.f, 0.f, 0.f};
            float sc1[4] = {0.f, 0.f, 0.f, 0.f};
            #pragma unroll
            for (int kk = 0; kk < 4; kk++) {
                uint32_t b0, b1, b2, b3;
                ldsm4(b0, b1, b2, b3,
                      sb + KF_O + kln + (uint32_t)kp * (16 * KP) + kk * 32);
                mma_fp16(sc0, qf[kk], b0, b1);
                mma_fp16(sc1, qf[kk], b2, b3);
            }

            uint32_t ph[4];
            {
                int col0 = ko + 16 * kp + 2 * t;
                uint16_t bA0 = *(const uint16_t*)(BN + (uint32_t)(m0 + g) * BP + col0);
                uint16_t bB0 = *(const uint16_t*)(BN + (uint32_t)(m0 + g + 8) * BP + col0);
                uint16_t bA1 = *(const uint16_t*)(BN + (uint32_t)(m0 + g) * BP + col0 + 8);
                uint16_t bB1 = *(const uint16_t*)(BN + (uint32_t)(m0 + g + 8) * BP + col0 + 8);
                float p0 = fast_exp2(sc0[0] + zt[bA0 & 0xFF]);
                float p1 = fast_exp2(sc0[1] + zt[bA0 >> 8]);
                float p2 = fast_exp2(sc0[2] + zt[bB0 & 0xFF]);
                float p3 = fast_exp2(sc0[3] + zt[bB0 >> 8]);
                ph[0] = pack2h(p0, p1);
                ph[1] = pack2h(p2, p3);
                p0 = fast_exp2(sc1[0] + zt[bA1 & 0xFF]);
                p1 = fast_exp2(sc1[1] + zt[bA1 >> 8]);
                p2 = fast_exp2(sc1[2] + zt[bB1 & 0xFF]);
                p3 = fast_exp2(sc1[3] + zt[bB1 >> 8]);
                ph[2] = pack2h(p0, p1);
                ph[3] = pack2h(p2, p3);
            }

            mma_fp16(lc, ph, ONES2, ONES2);       // l partial over this k16
            #pragma unroll
            for (int jjp = 0; jjp < 4; jjp++) {
                uint32_t v0, v1, v2, v3;
                ldsm4(v0, v1, v2, v3,
                      sb + VT_O + vln + (uint32_t)jjp * (16 * VP) + kp * 32);
                mma_fp16(oc[2 * jjp],     ph, v0, v1);
                mma_fp16(oc[2 * jjp + 1], ph, v2, v3);
            }
        }
        __syncthreads();
    }

    // ---- cross-warp reduction: key-half 1 stages partials, half 0 combines ----
    float* red = (float*)smem;            // 64 rows x 68 floats (O cols + l at 64)
    __syncthreads();
    if (hf == 1) {
        #pragma unroll
        for (int jj = 0; jj < 8; jj++) {
            int c = 8 * jj + 2 * t;
            red[(m0 + g) * 68 + c]         = oc[jj][0];
            red[(m0 + g) * 68 + c + 1]     = oc[jj][1];
            red[(m0 + g + 8) * 68 + c]     = oc[jj][2];
            red[(m0 + g + 8) * 68 + c + 1] = oc[jj][3];
        }
        if (t == 0) {
            red[(m0 + g) * 68 + 64]     = lc[0];
            red[(m0 + g + 8) * 68 + 64] = lc[2];
        }
    }
    __syncthreads();
    if (hf == 0) {
        float inv0 = 1.0f / (lc[0] + red[(m0 + g) * 68 + 64]);
        float inv1 = 1.0f / (lc[2] + red[(m0 + g + 8) * 68 + 64]);
        int r0 = q0 + m0 + g, r1 = r0 + 8;
        #pragma unroll
        for (int jj = 0; jj < 8; jj++) {
            int c = 8 * jj + 2 * t;
            int col = h * HDIM + c;
            float v00 = (oc[jj][0] + red[(m0 + g) * 68 + c]) * inv0;
            float v01 = (oc[jj][1] + red[(m0 + g) * 68 + c + 1]) * inv0;
            float v10 = (oc[jj][2] + red[(m0 + g + 8) * 68 + c]) * inv1;
            float v11 = (oc[jj][3] + red[(m0 + g + 8) * 68 + c + 1]) * inv1;
            __nv_bfloat16 h00 = __float2bfloat16_rn(v00);
            __nv_bfloat16 h01 = __float2bfloat16_rn(v01);
            __nv_bfloat16 h10 = __float2bfloat16_rn(v10);
            __nv_bfloat16 h11 = __float2bfloat16_rn(v11);
            __nv_bfloat162 u0; u0.x = h00; u0.y = h01;
            __nv_bfloat162 u1; u1.x = h10; u1.y = h11;
            *(uint32_t*)&g_AOh[(size_t)r0 * DMOD + col] = *(uint32_t*)&u0;
            *(uint32_t*)&g_AOh[(size_t)r1 * DMOD + col] = *(uint32_t*)&u1;
            *(uint32_t*)&g_AOl[(size_t)r0 * DMOD + col] =
                pack2bf(v00 - __bfloat162float(h00), v01 - __bfloat162float(h01));
            *(uint32_t*)&g_AOl[(size_t)r1 * DMOD + col] =
                pack2bf(v10 - __bfloat162float(h10), v11 - __bfloat162float(h11));
        }
    }
}

// ---------------------------------------------------------------------------

extern "C" void kernel_launch(void* const* d_in, const int* in_sizes, int n_in,
                              void* d_out, int out_size)
{
    const float* x  = (const float*)d_in[0];
    const float* z  = (const float*)d_in[1];
    const float* Wq = (const float*)d_in[2];
    const float* bq = (const float*)d_in[3];
    const float* Wk = (const float*)d_in[4];
    const float* bk = (const float*)d_in[5];
    const float* Wv = (const float*)d_in[6];
    const float* bv = (const float*)d_in[7];
    const float* Wo = (const float*)d_in[8];
    const float* bo = (const float*)d_in[9];
    const float* zt = (const float*)d_in[10];
    float* out = (float*)d_out;

    cudaFuncSetAttribute(attn_mma_kernel,
                         cudaFuncAttributeMaxDynamicSharedMemorySize, ATTN_SMEM);
    cudaFuncSetAttribute(gemm_mma_kernel,
                         cudaFuncAttributeMaxDynamicSharedMemorySize, GEMM_SMEM);

    // fused prep: bins + W transpose/split + x split
    prep_in_kernel<<<9216, 256>>>(x, z, Wq, Wk, Wv, Wo);

    // fused QKV projection; epilogue emits Qf/Kf (fp16) and Vc (fp32)
    gemm_mma_kernel<<<dim3(12, 16), 256, GEMM_SMEM>>>(0, bq, bk, bv, nullptr);

    // V transpose -> fp16 [h][d][2048]
    prep_vt_kernel<<<1024, 256>>>();

    // attention: 64 q-rows, key-split warps, 2 CTAs/SM
    attn_mma_kernel<<<dim3(NTOK / 64, NH), 256, ATTN_SMEM>>>(zt);

    // output projection
    gemm_mma_kernel<<<dim3(4, 16), 256, GEMM_SMEM>>>(1, bo, nullptr, nullptr, out);
}

// round 11
// speedup vs baseline: 1.2049x; 1.2049x over previous
#include <cuda_runtime.h>
#include <cuda_bf16.h>
#include <cuda_fp16.h>
#include <math.h>
#include <stdint.h>

#define NTOK 2048
#define DMOD 512
#define NH 8
#define HDIM 64
#define NBINS 16

// ---------------------------------------------------------------------------
// Scratch (no cudaMalloc). Only referenced from DEVICE code.
// ---------------------------------------------------------------------------
__device__ float g_Vc[NTOK * DMOD];                        // V proj (fp32, compact)
__device__ __half g_Xh[NTOK * DMOD], g_Xl[NTOK * DMOD];    // split x (fp16 hi/lo)
__device__ __half g_Wt[1536 * 512];                        // (Wq|Wk|Wv)^T fp16
__device__ __half g_Wot[512 * 512];                        // Wo^T fp16
__device__ __half g_AOh[NTOK * DMOD], g_AOl[NTOK * DMOD];  // attn out split fp16
__device__ __half g_Qf[NTOK * DMOD];                       // [h][tok][64] fp16
__device__ __half g_Kf[NTOK * DMOD];                       // [h][tok][64] fp16
__device__ __half g_Vtf[NTOK * DMOD];                      // [h][d][2048] fp16
__device__ uint8_t g_bins[NTOK * NTOK];

#define LOG2E 1.4426950408889634f

// ---------------------------------------------------------------------------
// mma.sync / cp.async / ldmatrix helpers
// ---------------------------------------------------------------------------
__device__ __forceinline__ void mma_fp16(float* c, const uint32_t* a,
                                         uint32_t b0, uint32_t b1) {
    asm volatile(
        "mma.sync.aligned.m16n8k16.row.col.f32.f16.f16.f32 "
        "{%0,%1,%2,%3},{%4,%5,%6,%7},{%8,%9},{%0,%1,%2,%3};"
        : "+f"(c[0]), "+f"(c[1]), "+f"(c[2]), "+f"(c[3])
        : "r"(a[0]), "r"(a[1]), "r"(a[2]), "r"(a[3]), "r"(b0), "r"(b1));
}
__device__ __forceinline__ void ldsm4(uint32_t& r0, uint32_t& r1,
                                      uint32_t& r2, uint32_t& r3, uint32_t addr) {
    asm volatile("ldmatrix.sync.aligned.m8n8.x4.shared.b16 {%0,%1,%2,%3}, [%4];"
                 : "=r"(r0), "=r"(r1), "=r"(r2), "=r"(r3) : "r"(addr));
}
__device__ __forceinline__ void cp16(uint32_t dst, const void* src) {
    asm volatile("cp.async.cg.shared.global [%0], [%1], 16;" :: "r"(dst), "l"(src));
}
__device__ __forceinline__ uint32_t smem_u32(const void* p) {
    uint32_t a;
    asm("{ .reg .u64 t; cvta.to.shared.u64 t, %1; cvt.u32.u64 %0, t; }"
        : "=r"(a) : "l"(p));
    return a;
}
__device__ __forceinline__ uint32_t pack2h(float a, float b) {
    __half2 t;
    t.x = __float2half_rn(a);
    t.y = __float2half_rn(b);
    return *(uint32_t*)&t;
}
__device__ __forceinline__ float fast_exp2(float x) {
    float r;
    asm("ex2.approx.ftz.f32 %0, %1;" : "=f"(r) : "f"(x));
    return r;
}

// ---------------------------------------------------------------------------
// 2-term split-fp16 tensor-core GEMM:
//   C = (Ah + Al)[M x 512] * (Bt[N x 512])^T  (+ bias)
// Error ~2^-12 relative: below the fp16 rounding consumers already apply.
// mode 0: QKV projection -> g_Qf/g_Kf (fp16) + g_Vc (fp32).
// mode 1: out projection -> C_ext fp32.
// ---------------------------------------------------------------------------
#define GPIT 80
#define GAH 0
#define GAL 10240
#define GB  20480
#define GSTAGE 30720
#define GEMM_SMEM (2 * GSTAGE)

__global__ __launch_bounds__(256, 2) void gemm_mma_kernel(
    int mode, const float* __restrict__ b0p, const float* __restrict__ b1p,
    const float* __restrict__ b2p, float* __restrict__ C_ext)
{
    extern __shared__ char smem[];
    const __half *Ah, *Al, *Bt;
    if (mode == 0) {
        Ah = g_Xh;  Al = g_Xl;  Bt = g_Wt;
    } else {
        Ah = g_AOh; Al = g_AOl; Bt = g_Wot;
    }

    const int tid = threadIdx.x;
    const int w = tid >> 5, l = tid & 31, g = l >> 2, t = l & 3;
    const int q4 = l >> 3, r8 = l & 7;
    const int n0 = blockIdx.x * 128;
    const int mb = blockIdx.y * 128;
    const uint32_t sbase = smem_u32(smem);

    const uint32_t aln = (uint32_t)(w * 16 + 8 * (q4 & 1) + r8) * GPIT + 16 * (q4 >> 1);
    const uint32_t bln = (uint32_t)(8 * (q4 >> 1) + r8) * GPIT + 16 * (q4 & 1);

    auto load = [&](int kc, int st) {
        uint32_t b = sbase + st * GSTAGE;
        #pragma unroll
        for (int p = 0; p < 2; p++) {
            int i = tid + p * 256;
            int r = i >> 2, c = i & 3;
            uint32_t so = r * GPIT + c * 16;
            size_t ga = ((size_t)(mb + r) * 512 + kc * 32) * 2 + c * 16;
            cp16(b + GAH + so, (const char*)Ah + ga);
            cp16(b + GAL + so, (const char*)Al + ga);
            size_t gb = ((size_t)(n0 + r) * 512 + kc * 32) * 2 + c * 16;
            cp16(b + GB + so, (const char*)Bt + gb);
        }
        asm volatile("cp.async.commit_group;" ::: "memory");
    };

    float acc[16][4];
    #pragma unroll
    for (int j = 0; j < 16; j++)
        #pragma unroll
        for (int i = 0; i < 4; i++) acc[j][i] = 0.0f;

    load(0, 0);
    for (int kc = 0; kc < 16; kc++) {
        if (kc + 1 < 16) {
            load(kc + 1, (kc + 1) & 1);
            asm volatile("cp.async.wait_group 1;" ::: "memory");
        } else {
            asm volatile("cp.async.wait_group 0;" ::: "memory");
        }
        __syncthreads();
        const uint32_t sb = sbase + (kc & 1) * GSTAGE;

        #pragma unroll
        for (int kk = 0; kk < 2; kk++) {
            uint32_t ah[4], al[4];
            ldsm4(ah[0], ah[1], ah[2], ah[3], sb + GAH + aln + kk * 32);
            ldsm4(al[0], al[1], al[2], al[3], sb + GAL + aln + kk * 32);
            #pragma unroll
            for (int jp = 0; jp < 8; jp++) {
                uint32_t b0, b1, b2, b3;
                ldsm4(b0, b1, b2, b3, sb + GB + bln + (uint32_t)jp * (16 * GPIT) + kk * 32);
                mma_fp16(acc[2 * jp],     ah, b0, b1);
                mma_fp16(acc[2 * jp],     al, b0, b1);
                mma_fp16(acc[2 * jp + 1], ah, b2, b3);
                mma_fp16(acc[2 * jp + 1], al, b2, b3);
            }
        }
        __syncthreads();
    }

    const int r0 = mb + w * 16 + g, r1 = r0 + 8;
    if (mode == 1) {
        #pragma unroll
        for (int j = 0; j < 16; j++) {
            int col = n0 + 8 * j + 2 * t;
            float bv0 = b0p[col], bv1 = b0p[col + 1];
            *(float2*)&C_ext[(size_t)r0 * 512 + col] =
                make_float2(acc[j][0] + bv0, acc[j][1] + bv1);
            *(float2*)&C_ext[(size_t)r1 * 512 + col] =
                make_float2(acc[j][2] + bv0, acc[j][3] + bv1);
        }
    } else {
        const float QS = 0.125f * LOG2E;
        #pragma unroll
        for (int j = 0; j < 16; j++) {
            int col = n0 + 8 * j + 2 * t;
            const float* bp = (col < 512) ? b0p : (col < 1024 ? b1p : b2p);
            int cc = col & 511;
            float bv0 = bp[cc], bv1 = bp[cc + 1];
            float v00 = acc[j][0] + bv0, v01 = acc[j][1] + bv1;
            float v10 = acc[j][2] + bv0, v11 = acc[j][3] + bv1;
            if (col < 512) {
                int h = cc >> 6, d = cc & 63;
                *(uint32_t*)&g_Qf[((size_t)h * NTOK + r0) * HDIM + d] =
                    pack2h(v00 * QS, v01 * QS);
                *(uint32_t*)&g_Qf[((size_t)h * NTOK + r1) * HDIM + d] =
                    pack2h(v10 * QS, v11 * QS);
            } else if (col < 1024) {
                int h = cc >> 6, d = cc & 63;
                *(uint32_t*)&g_Kf[((size_t)h * NTOK + r0) * HDIM + d] = pack2h(v00, v01);
                *(uint32_t*)&g_Kf[((size_t)h * NTOK + r1) * HDIM + d] = pack2h(v10, v11);
            } else {
                *(float2*)&g_Vc[(size_t)r0 * 512 + cc] = make_float2(v00, v01);
                *(float2*)&g_Vc[(size_t)r1 * 512 + cc] = make_float2(v10, v11);
            }
        }
    }
}

// ---------------------------------------------------------------------------
// Fused input prep:
//   blocks [0,4096): z bins  |  [4096,5120): W transpose (fp16)  |  [5120,9216): x split fp16
// ---------------------------------------------------------------------------
__device__ __forceinline__ uint8_t bin_of(float z) {
    int b = (int)floorf(z / 5.0f * 16.0f);
    return (uint8_t)max(0, min(NBINS - 1, b));
}

__global__ __launch_bounds__(256) void prep_in_kernel(
    const float* __restrict__ x, const float* __restrict__ zmat,
    const float* __restrict__ Wq, const float* __restrict__ Wk,
    const float* __restrict__ Wv, const float* __restrict__ Wo)
{
    int bx = blockIdx.x;
    int tid = threadIdx.x;
    if (bx < 4096) {
        size_t i = (size_t)bx * 256 + tid;
        float4 z = *(const float4*)(zmat + i * 4);
        uchar4 b;
        b.x = bin_of(z.x); b.y = bin_of(z.y); b.z = bin_of(z.z); b.w = bin_of(z.w);
        *(uchar4*)(g_bins + i * 4) = b;
    } else if (bx < 5120) {
        __shared__ float ts[32][33];
        int bb = bx - 4096;
        int zb = bb >> 8, rem = bb & 255;
        int k0 = (rem & 15) * 32;
        int n0 = (rem >> 4) * 32;
        const float* src;
        __half* dh;
        int nbase;
        if (zb == 0)      { src = Wq; dh = g_Wt;  nbase = 0; }
        else if (zb == 1) { src = Wk; dh = g_Wt;  nbase = 512; }
        else if (zb == 2) { src = Wv; dh = g_Wt;  nbase = 1024; }
        else              { src = Wo; dh = g_Wot; nbase = 0; }
        int tx = tid & 31, ty = tid >> 5;
        #pragma unroll
        for (int i = 0; i < 4; i++) {
            int r = ty + i * 8;
            ts[r][tx] = src[(size_t)(k0 + r) * 512 + n0 + tx];
        }
        __syncthreads();
        #pragma unroll
        for (int i = 0; i < 4; i++) {
            int nn = ty + i * 8;
            dh[(size_t)(nbase + n0 + nn) * 512 + k0 + tx] = __float2half_rn(ts[tx][nn]);
        }
    } else {
        int i = (bx - 5120) * 256 + tid;
        float v = x[i];
        __half h = __float2half_rn(v);
        g_Xh[i] = h;
        g_Xl[i] = __float2half_rn(v - __half2float(h));
    }
}

// ---------------------------------------------------------------------------
// V transpose: g_Vc [tok][512] fp32 -> g_Vtf [h][d][2048] fp16
// ---------------------------------------------------------------------------
__global__ __launch_bounds__(256) void prep_vt_kernel()
{
    __shared__ float ts[32][33];
    int bx = blockIdx.x;
    int tok0 = (bx & 63) * 32;
    int c0   = (bx >> 6) * 32;
    int tid = threadIdx.x;
    int tx = tid & 31, ty = tid >> 5;
    #pragma unroll
    for (int i = 0; i < 4; i++) {
        int r = ty + i * 8;
        ts[r][tx] = g_Vc[(size_t)(tok0 + r) * 512 + c0 + tx];
    }
    __syncthreads();
    #pragma unroll
    for (int i = 0; i < 4; i++) {
        int dd = ty + i * 8;
        int col = c0 + dd, h = col >> 6, hd = col & 63;
        g_Vtf[((size_t)h * HDIM + hd) * NTOK + tok0 + tx] = __float2half_rn(ts[tx][dd]);
    }
}

// ---------------------------------------------------------------------------
// fp16 mma.sync flash attention (best variant, R9): 128 q-rows, 8 warps,
// ldmatrix.x4 operand loads. Writes split-fp16 AO for the outproj GEMM.
// ---------------------------------------------------------------------------
#define KP 144
#define VP 272
#define BP 144
#define KF_O 0
#define VT_O 18432
#define BN_O 35840
#define STAGE 54272
#define ATTN_SMEM (2 * STAGE)

__global__ __launch_bounds__(256, 1) void attn_mma_kernel(const float* __restrict__ ztab)
{
    extern __shared__ char smem[];
    __shared__ float zt[NBINS];

    const int tid = threadIdx.x;
    const int w   = tid >> 5;
    const int l   = tid & 31;
    const int g   = l >> 2;
    const int t   = l & 3;
    const int q4  = l >> 3, r8 = l & 7;
    const int h   = blockIdx.y;
    const int q0  = blockIdx.x * 128;
    const int m0  = w * 16;
    const uint32_t ONES2 = 0x3C003C00u;   // fp16 (1.0, 1.0)

    if (tid < NBINS) zt[tid] = ztab[tid * NH + h] * LOG2E;

    const uint32_t sbase = smem_u32(smem);

    const uint32_t kln = (uint32_t)(8 * (q4 >> 1) + r8) * KP + 16 * (q4 & 1);
    const uint32_t vln = (uint32_t)(8 * (q4 >> 1) + r8) * VP + 16 * (q4 & 1);

    auto load_tile = [&](int kt, int stage) {
        uint32_t base = sbase + stage * STAGE;
        #pragma unroll
        for (int p = 0; p < 4; p++) {
            int i = tid + p * 256;
            int r = i >> 3, c = i & 7;
            cp16(base + KF_O + r * KP + c * 16,
                 (const char*)g_Kf + (((size_t)h * NTOK + kt * 128 + r) * HDIM) * 2 + c * 16);
        }
        #pragma unroll
        for (int p = 0; p < 4; p++) {
            int i = tid + p * 256;
            int d = i >> 4, c = i & 15;
            cp16(base + VT_O + d * VP + c * 16,
                 (const char*)g_Vtf + (((size_t)h * HDIM + d) * NTOK + kt * 128) * 2 + c * 16);
        }
        #pragma unroll
        for (int p = 0; p < 4; p++) {
            int i = tid + p * 256;
            int r = i >> 3, c = i & 7;
            cp16(base + BN_O + r * BP + c * 16,
                 g_bins + (size_t)(q0 + r) * NTOK + kt * 128 + c * 16);
        }
        asm volatile("cp.async.commit_group;" ::: "memory");
    };

    load_tile(0, 0);

    uint32_t qf[4][4];
    {
        const uint16_t* qb = (const uint16_t*)g_Qf + ((size_t)h * NTOK + q0 + m0) * HDIM;
        #pragma unroll
        for (int kk = 0; kk < 4; kk++) {
            int c0 = 16 * kk + 2 * t;
            qf[kk][0] = *(const uint32_t*)(qb + (size_t)g * HDIM + c0);
            qf[kk][1] = *(const uint32_t*)(qb + (size_t)(g + 8) * HDIM + c0);
            qf[kk][2] = *(const uint32_t*)(qb + (size_t)g * HDIM + c0 + 8);
            qf[kk][3] = *(const uint32_t*)(qb + (size_t)(g + 8) * HDIM + c0 + 8);
        }
    }

    float oc[8][4];
    #pragma unroll
    for (int j = 0; j < 8; j++)
        #pragma unroll
        for (int i = 0; i < 4; i++) oc[j][i] = 0.0f;
    float lc[4] = {0.0f, 0.0f, 0.0f, 0.0f};

    for (int kt = 0; kt < NTOK / 128; kt++) {
        if (kt + 1 < NTOK / 128) {
            load_tile(kt + 1, (kt + 1) & 1);
            asm volatile("cp.async.wait_group 1;" ::: "memory");
        } else {
            asm volatile("cp.async.wait_group 0;" ::: "memory");
        }
        __syncthreads();

        const uint32_t sb = sbase + (kt & 1) * STAGE;
        const char* S = smem + (kt & 1) * STAGE;

        float sc[16][4];
        #pragma unroll
        for (int j = 0; j < 16; j++)
            #pragma unroll
            for (int i = 0; i < 4; i++) sc[j][i] = 0.0f;

        #pragma unroll
        for (int kk = 0; kk < 4; kk++) {
            #pragma unroll
            for (int jp = 0; jp < 8; jp++) {
                uint32_t b0, b1, b2, b3;
                ldsm4(b0, b1, b2, b3, sb + KF_O + kln + (uint32_t)jp * (16 * KP) + kk * 32);
                mma_fp16(sc[2 * jp],     qf[kk], b0, b1);
                mma_fp16(sc[2 * jp + 1], qf[kk], b2, b3);
            }
        }

        uint32_t ph[8][4];
        const char* BN = S + BN_O;
        #pragma unroll
        for (int j = 0; j < 16; j++) {
            int col = 8 * j + 2 * t;
            uint16_t bA = *(const uint16_t*)(BN + (uint32_t)(m0 + g) * BP + col);
            uint16_t bB = *(const uint16_t*)(BN + (uint32_t)(m0 + g + 8) * BP + col);
            float p0 = fast_exp2(sc[j][0] + zt[bA & 0xFF]);
            float p1 = fast_exp2(sc[j][1] + zt[bA >> 8]);
            float p2 = fast_exp2(sc[j][2] + zt[bB & 0xFF]);
            float p3 = fast_exp2(sc[j][3] + zt[bB >> 8]);
            int kp = j >> 1, hf = (j & 1) * 2;
            ph[kp][hf + 0] = pack2h(p0, p1);
            ph[kp][hf + 1] = pack2h(p2, p3);
        }

        #pragma unroll
        for (int kp = 0; kp < 8; kp++) {
            mma_fp16(lc, ph[kp], ONES2, ONES2);
            #pragma unroll
            for (int jjp = 0; jjp < 4; jjp++) {
                uint32_t v0, v1, v2, v3;
                ldsm4(v0, v1, v2, v3, sb + VT_O + vln + (uint32_t)jjp * (16 * VP) + kp * 32);
                mma_fp16(oc[2 * jjp],     ph[kp], v0, v1);
                mma_fp16(oc[2 * jjp + 1], ph[kp], v2, v3);
            }
        }
        __syncthreads();
    }

    float inv0 = 1.0f / lc[0], inv1 = 1.0f / lc[2];

    int r0 = q0 + m0 + g, r1 = r0 + 8;
    #pragma unroll
    for (int jj = 0; jj < 8; jj++) {
        int col = h * HDIM + 8 * jj + 2 * t;
        float v00 = oc[jj][0] * inv0, v01 = oc[jj][1] * inv0;
        float v10 = oc[jj][2] * inv1, v11 = oc[jj][3] * inv1;
        __half h00 = __float2half_rn(v00);
        __half h01 = __float2half_rn(v01);
        __half h10 = __float2half_rn(v10);
        __half h11 = __float2half_rn(v11);
        __half2 u0; u0.x = h00; u0.y = h01;
        __half2 u1; u1.x = h10; u1.y = h11;
        *(uint32_t*)&g_AOh[(size_t)r0 * DMOD + col] = *(uint32_t*)&u0;
        *(uint32_t*)&g_AOh[(size_t)r1 * DMOD + col] = *(uint32_t*)&u1;
        *(uint32_t*)&g_AOl[(size_t)r0 * DMOD + col] =
            pack2h(v00 - __half2float(h00), v01 - __half2float(h01));
        *(uint32_t*)&g_AOl[(size_t)r1 * DMOD + col] =
            pack2h(v10 - __half2float(h10), v11 - __half2float(h11));
    }
}

// ---------------------------------------------------------------------------

extern "C" void kernel_launch(void* const* d_in, const int* in_sizes, int n_in,
                              void* d_out, int out_size)
{
    const float* x  = (const float*)d_in[0];
    const float* z  = (const float*)d_in[1];
    const float* Wq = (const float*)d_in[2];
    const float* bq = (const float*)d_in[3];
    const float* Wk = (const float*)d_in[4];
    const float* bk = (const float*)d_in[5];
    const float* Wv = (const float*)d_in[6];
    const float* bv = (const float*)d_in[7];
    const float* Wo = (const float*)d_in[8];
    const float* bo = (const float*)d_in[9];
    const float* zt = (const float*)d_in[10];
    float* out = (float*)d_out;

    cudaFuncSetAttribute(attn_mma_kernel,
                         cudaFuncAttributeMaxDynamicSharedMemorySize, ATTN_SMEM);
    cudaFuncSetAttribute(gemm_mma_kernel,
                         cudaFuncAttributeMaxDynamicSharedMemorySize, GEMM_SMEM);

    // fused prep: bins + W transpose (fp16) + x split (fp16)
    prep_in_kernel<<<9216, 256>>>(x, z, Wq, Wk, Wv, Wo);

    // fused QKV projection (2-term fp16); epilogue emits Qf/Kf (fp16), Vc (fp32)
    gemm_mma_kernel<<<dim3(12, 16), 256, GEMM_SMEM>>>(0, bq, bk, bv, nullptr);

    // V transpose -> fp16 [h][d][2048]
    prep_vt_kernel<<<1024, 256>>>();

    // attention (best R9 variant)
    attn_mma_kernel<<<dim3(NTOK / 128, NH), 256, ATTN_SMEM>>>(zt);

    // output projection (2-term fp16)
    gemm_mma_kernel<<<dim3(4, 16), 256, GEMM_SMEM>>>(1, bo, nullptr, nullptr, out);
}

// round 12
// speedup vs baseline: 1.2298x; 1.0206x over previous
#include <cuda_runtime.h>
#include <cuda_fp16.h>
#include <math.h>
#include <stdint.h>

#define NTOK 2048
#define DMOD 512
#define NH 8
#define HDIM 64
#define NBINS 16

// ---------------------------------------------------------------------------
// Scratch (no cudaMalloc). Only referenced from DEVICE code.
// ---------------------------------------------------------------------------
__device__ __half g_Xh[NTOK * DMOD], g_Xl[NTOK * DMOD];    // split x (fp16 hi/lo)
__device__ __half g_Wt[1536 * 512];                        // (Wq|Wk|Wv)^T fp16
__device__ __half g_Wot[512 * 512];                        // Wo^T fp16
__device__ __half g_AOh[NTOK * DMOD], g_AOl[NTOK * DMOD];  // attn out split fp16
__device__ __half g_Qf[NTOK * DMOD];                       // [h][tok][64] fp16
__device__ __half g_Kf[NTOK * DMOD];                       // [h][tok][64] fp16
__device__ __half g_Vf[NTOK * DMOD];                       // [h][tok][64] fp16
__device__ uint8_t g_bins[NTOK * NTOK];

#define LOG2E 1.4426950408889634f

// ---------------------------------------------------------------------------
// mma.sync / cp.async / ldmatrix helpers
// ---------------------------------------------------------------------------
__device__ __forceinline__ void mma_fp16(float* c, const uint32_t* a,
                                         uint32_t b0, uint32_t b1) {
    asm volatile(
        "mma.sync.aligned.m16n8k16.row.col.f32.f16.f16.f32 "
        "{%0,%1,%2,%3},{%4,%5,%6,%7},{%8,%9},{%0,%1,%2,%3};"
        : "+f"(c[0]), "+f"(c[1]), "+f"(c[2]), "+f"(c[3])
        : "r"(a[0]), "r"(a[1]), "r"(a[2]), "r"(a[3]), "r"(b0), "r"(b1));
}
__device__ __forceinline__ void ldsm4(uint32_t& r0, uint32_t& r1,
                                      uint32_t& r2, uint32_t& r3, uint32_t addr) {
    asm volatile("ldmatrix.sync.aligned.m8n8.x4.shared.b16 {%0,%1,%2,%3}, [%4];"
                 : "=r"(r0), "=r"(r1), "=r"(r2), "=r"(r3) : "r"(addr));
}
__device__ __forceinline__ void ldsm4t(uint32_t& r0, uint32_t& r1,
                                       uint32_t& r2, uint32_t& r3, uint32_t addr) {
    asm volatile("ldmatrix.sync.aligned.m8n8.x4.trans.shared.b16 {%0,%1,%2,%3}, [%4];"
                 : "=r"(r0), "=r"(r1), "=r"(r2), "=r"(r3) : "r"(addr));
}
__device__ __forceinline__ void cp16(uint32_t dst, const void* src) {
    asm volatile("cp.async.cg.shared.global [%0], [%1], 16;" :: "r"(dst), "l"(src));
}
__device__ __forceinline__ uint32_t smem_u32(const void* p) {
    uint32_t a;
    asm("{ .reg .u64 t; cvta.to.shared.u64 t, %1; cvt.u32.u64 %0, t; }"
        : "=r"(a) : "l"(p));
    return a;
}
__device__ __forceinline__ uint32_t pack2h(float a, float b) {
    __half2 t;
    t.x = __float2half_rn(a);
    t.y = __float2half_rn(b);
    return *(uint32_t*)&t;
}
__device__ __forceinline__ float fast_exp2(float x) {
    float r;
    asm("ex2.approx.ftz.f32 %0, %1;" : "=f"(r) : "f"(x));
    return r;
}

// ---------------------------------------------------------------------------
// 2-term split-fp16 tensor-core GEMM (validated R11):
//   C = (Ah + Al)[M x 512] * (Bt[N x 512])^T  (+ bias)
// mode 0: QKV projection -> g_Qf/g_Kf/g_Vf (fp16, per-head layouts).
// mode 1: out projection -> C_ext fp32.
// ---------------------------------------------------------------------------
#define GPIT 80
#define GAH 0
#define GAL 10240
#define GB  20480
#define GSTAGE 30720
#define GEMM_SMEM (2 * GSTAGE)

__global__ __launch_bounds__(256, 2) void gemm_mma_kernel(
    int mode, const float* __restrict__ b0p, const float* __restrict__ b1p,
    const float* __restrict__ b2p, float* __restrict__ C_ext)
{
    extern __shared__ char smem[];
    const __half *Ah, *Al, *Bt;
    if (mode == 0) {
        Ah = g_Xh;  Al = g_Xl;  Bt = g_Wt;
    } else {
        Ah = g_AOh; Al = g_AOl; Bt = g_Wot;
    }

    const int tid = threadIdx.x;
    const int w = tid >> 5, l = tid & 31, g = l >> 2, t = l & 3;
    const int q4 = l >> 3, r8 = l & 7;
    const int n0 = blockIdx.x * 128;
    const int mb = blockIdx.y * 128;
    const uint32_t sbase = smem_u32(smem);

    const uint32_t aln = (uint32_t)(w * 16 + 8 * (q4 & 1) + r8) * GPIT + 16 * (q4 >> 1);
    const uint32_t bln = (uint32_t)(8 * (q4 >> 1) + r8) * GPIT + 16 * (q4 & 1);

    auto load = [&](int kc, int st) {
        uint32_t b = sbase + st * GSTAGE;
        #pragma unroll
        for (int p = 0; p < 2; p++) {
            int i = tid + p * 256;
            int r = i >> 2, c = i & 3;
            uint32_t so = r * GPIT + c * 16;
            size_t ga = ((size_t)(mb + r) * 512 + kc * 32) * 2 + c * 16;
            cp16(b + GAH + so, (const char*)Ah + ga);
            cp16(b + GAL + so, (const char*)Al + ga);
            size_t gb = ((size_t)(n0 + r) * 512 + kc * 32) * 2 + c * 16;
            cp16(b + GB + so, (const char*)Bt + gb);
        }
        asm volatile("cp.async.commit_group;" ::: "memory");
    };

    float acc[16][4];
    #pragma unroll
    for (int j = 0; j < 16; j++)
        #pragma unroll
        for (int i = 0; i < 4; i++) acc[j][i] = 0.0f;

    load(0, 0);
    for (int kc = 0; kc < 16; kc++) {
        if (kc + 1 < 16) {
            load(kc + 1, (kc + 1) & 1);
            asm volatile("cp.async.wait_group 1;" ::: "memory");
        } else {
            asm volatile("cp.async.wait_group 0;" ::: "memory");
        }
        __syncthreads();
        const uint32_t sb = sbase + (kc & 1) * GSTAGE;

        #pragma unroll
        for (int kk = 0; kk < 2; kk++) {
            uint32_t ah[4], al[4];
            ldsm4(ah[0], ah[1], ah[2], ah[3], sb + GAH + aln + kk * 32);
            ldsm4(al[0], al[1], al[2], al[3], sb + GAL + aln + kk * 32);
            #pragma unroll
            for (int jp = 0; jp < 8; jp++) {
                uint32_t b0, b1, b2, b3;
                ldsm4(b0, b1, b2, b3, sb + GB + bln + (uint32_t)jp * (16 * GPIT) + kk * 32);
                mma_fp16(acc[2 * jp],     ah, b0, b1);
                mma_fp16(acc[2 * jp],     al, b0, b1);
                mma_fp16(acc[2 * jp + 1], ah, b2, b3);
                mma_fp16(acc[2 * jp + 1], al, b2, b3);
            }
        }
        __syncthreads();
    }

    const int r0 = mb + w * 16 + g, r1 = r0 + 8;
    if (mode == 1) {
        #pragma unroll
        for (int j = 0; j < 16; j++) {
            int col = n0 + 8 * j + 2 * t;
            float bv0 = b0p[col], bv1 = b0p[col + 1];
            *(float2*)&C_ext[(size_t)r0 * 512 + col] =
                make_float2(acc[j][0] + bv0, acc[j][1] + bv1);
            *(float2*)&C_ext[(size_t)r1 * 512 + col] =
                make_float2(acc[j][2] + bv0, acc[j][3] + bv1);
        }
    } else {
        const float QS = 0.125f * LOG2E;
        #pragma unroll
        for (int j = 0; j < 16; j++) {
            int col = n0 + 8 * j + 2 * t;
            const float* bp = (col < 512) ? b0p : (col < 1024 ? b1p : b2p);
            int cc = col & 511;
            float bv0 = bp[cc], bv1 = bp[cc + 1];
            float v00 = acc[j][0] + bv0, v01 = acc[j][1] + bv1;
            float v10 = acc[j][2] + bv0, v11 = acc[j][3] + bv1;
            int h = cc >> 6, d = cc & 63;
            size_t d0 = ((size_t)h * NTOK + r0) * HDIM + d;
            size_t d1 = ((size_t)h * NTOK + r1) * HDIM + d;
            if (col < 512) {
                *(uint32_t*)&g_Qf[d0] = pack2h(v00 * QS, v01 * QS);
                *(uint32_t*)&g_Qf[d1] = pack2h(v10 * QS, v11 * QS);
            } else if (col < 1024) {
                *(uint32_t*)&g_Kf[d0] = pack2h(v00, v01);
                *(uint32_t*)&g_Kf[d1] = pack2h(v10, v11);
            } else {
                *(uint32_t*)&g_Vf[d0] = pack2h(v00, v01);
                *(uint32_t*)&g_Vf[d1] = pack2h(v10, v11);
            }
        }
    }
}

// ---------------------------------------------------------------------------
// Fused input prep:
//   blocks [0,4096): z bins | [4096,5120): W transpose (fp16) | [5120,9216): x split fp16
// ---------------------------------------------------------------------------
__device__ __forceinline__ uint8_t bin_of(float z) {
    int b = (int)floorf(z / 5.0f * 16.0f);
    return (uint8_t)max(0, min(NBINS - 1, b));
}

__global__ __launch_bounds__(256) void prep_in_kernel(
    const float* __restrict__ x, const float* __restrict__ zmat,
    const float* __restrict__ Wq, const float* __restrict__ Wk,
    const float* __restrict__ Wv, const float* __restrict__ Wo)
{
    int bx = blockIdx.x;
    int tid = threadIdx.x;
    if (bx < 4096) {
        size_t i = (size_t)bx * 256 + tid;
        float4 z = *(const float4*)(zmat + i * 4);
        uchar4 b;
        b.x = bin_of(z.x); b.y = bin_of(z.y); b.z = bin_of(z.z); b.w = bin_of(z.w);
        *(uchar4*)(g_bins + i * 4) = b;
    } else if (bx < 5120) {
        __shared__ float ts[32][33];
        int bb = bx - 4096;
        int zb = bb >> 8, rem = bb & 255;
        int k0 = (rem & 15) * 32;
        int n0 = (rem >> 4) * 32;
        const float* src;
        __half* dh;
        int nbase;
        if (zb == 0)      { src = Wq; dh = g_Wt;  nbase = 0; }
        else if (zb == 1) { src = Wk; dh = g_Wt;  nbase = 512; }
        else if (zb == 2) { src = Wv; dh = g_Wt;  nbase = 1024; }
        else              { src = Wo; dh = g_Wot; nbase = 0; }
        int tx = tid & 31, ty = tid >> 5;
        #pragma unroll
        for (int i = 0; i < 4; i++) {
            int r = ty + i * 8;
            ts[r][tx] = src[(size_t)(k0 + r) * 512 + n0 + tx];
        }
        __syncthreads();
        #pragma unroll
        for (int i = 0; i < 4; i++) {
            int nn = ty + i * 8;
            dh[(size_t)(nbase + n0 + nn) * 512 + k0 + tx] = __float2half_rn(ts[tx][nn]);
        }
    } else {
        int i = (bx - 5120) * 256 + tid;
        float v = x[i];
        __half h = __float2half_rn(v);
        g_Xh[i] = h;
        g_Xl[i] = __float2half_rn(v - __half2float(h));
    }
}

// ---------------------------------------------------------------------------
// fp16 mma.sync flash attention: 128 q-rows, 8 warps.
// K via ldmatrix; V via ldmatrix.trans from [tok][64] tiles (no V transpose
// kernel needed). l accumulated as fp32 FADDs in the exp loop (FMA pipe).
// ---------------------------------------------------------------------------
#define KP 144
#define VP 144
#define BP 144
#define KF_O 0
#define VT_O 18432
#define BN_O 36864
#define STAGE 55296
#define ATTN_SMEM (2 * STAGE)

__global__ __launch_bounds__(256, 1) void attn_mma_kernel(const float* __restrict__ ztab)
{
    extern __shared__ char smem[];
    __shared__ float zt[NBINS];

    const int tid = threadIdx.x;
    const int w   = tid >> 5;
    const int l   = tid & 31;
    const int g   = l >> 2;
    const int t   = l & 3;
    const int q4  = l >> 3, r8 = l & 7;
    const int h   = blockIdx.y;
    const int q0  = blockIdx.x * 128;
    const int m0  = w * 16;

    if (tid < NBINS) zt[tid] = ztab[tid * NH + h] * LOG2E;

    const uint32_t sbase = smem_u32(smem);

    // K (non-trans): matrix q4 -> key row 8*(q4>>1)+r8, dim half 16B*(q4&1)
    const uint32_t kln = (uint32_t)(8 * (q4 >> 1) + r8) * KP + 16 * (q4 & 1);
    // V (trans): matrix q4 -> tok row 8*(q4&1)+r8, d half 16B*(q4>>1)
    const uint32_t vln = (uint32_t)(8 * (q4 & 1) + r8) * VP + 16 * (q4 >> 1);

    auto load_tile = [&](int kt, int stage) {
        uint32_t base = sbase + stage * STAGE;
        #pragma unroll
        for (int p = 0; p < 4; p++) {       // K: 128 rows x 128B
            int i = tid + p * 256;
            int r = i >> 3, c = i & 7;
            cp16(base + KF_O + r * KP + c * 16,
                 (const char*)g_Kf + (((size_t)h * NTOK + kt * 128 + r) * HDIM) * 2 + c * 16);
        }
        #pragma unroll
        for (int p = 0; p < 4; p++) {       // V: 128 rows x 128B (same layout)
            int i = tid + p * 256;
            int r = i >> 3, c = i & 7;
            cp16(base + VT_O + r * VP + c * 16,
                 (const char*)g_Vf + (((size_t)h * NTOK + kt * 128 + r) * HDIM) * 2 + c * 16);
        }
        #pragma unroll
        for (int p = 0; p < 4; p++) {       // bins: 128 rows x 128B
            int i = tid + p * 256;
            int r = i >> 3, c = i & 7;
            cp16(base + BN_O + r * BP + c * 16,
                 g_bins + (size_t)(q0 + r) * NTOK + kt * 128 + c * 16);
        }
        asm volatile("cp.async.commit_group;" ::: "memory");
    };

    load_tile(0, 0);

    uint32_t qf[4][4];
    {
        const uint16_t* qb = (const uint16_t*)g_Qf + ((size_t)h * NTOK + q0 + m0) * HDIM;
        #pragma unroll
        for (int kk = 0; kk < 4; kk++) {
            int c0 = 16 * kk + 2 * t;
            qf[kk][0] = *(const uint32_t*)(qb + (size_t)g * HDIM + c0);
            qf[kk][1] = *(const uint32_t*)(qb + (size_t)(g + 8) * HDIM + c0);
            qf[kk][2] = *(const uint32_t*)(qb + (size_t)g * HDIM + c0 + 8);
            qf[kk][3] = *(const uint32_t*)(qb + (size_t)(g + 8) * HDIM + c0 + 8);
        }
    }

    float oc[8][4];
    #pragma unroll
    for (int j = 0; j < 8; j++)
        #pragma unroll
        for (int i = 0; i < 4; i++) oc[j][i] = 0.0f;
    float l0 = 0.0f, l1 = 0.0f;

    for (int kt = 0; kt < NTOK / 128; kt++) {
        if (kt + 1 < NTOK / 128) {
            load_tile(kt + 1, (kt + 1) & 1);
            asm volatile("cp.async.wait_group 1;" ::: "memory");
        } else {
            asm volatile("cp.async.wait_group 0;" ::: "memory");
        }
        __syncthreads();

        const uint32_t sb = sbase + (kt & 1) * STAGE;
        const char* BN = smem + (kt & 1) * STAGE + BN_O;

        // ---- S = Q K^T ----
        float sc[16][4];
        #pragma unroll
        for (int j = 0; j < 16; j++)
            #pragma unroll
            for (int i = 0; i < 4; i++) sc[j][i] = 0.0f;

        #pragma unroll
        for (int kk = 0; kk < 4; kk++) {
            #pragma unroll
            for (int jp = 0; jp < 8; jp++) {
                uint32_t b0, b1, b2, b3;
                ldsm4(b0, b1, b2, b3, sb + KF_O + kln + (uint32_t)jp * (16 * KP) + kk * 32);
                mma_fp16(sc[2 * jp],     qf[kk], b0, b1);
                mma_fp16(sc[2 * jp + 1], qf[kk], b2, b3);
            }
        }

        // ---- softmax: p = 2^(s + bias); l via FADD; pack A-fragments ----
        uint32_t ph[8][4];
        #pragma unroll
        for (int j = 0; j < 16; j++) {
            int col = 8 * j + 2 * t;
            uint16_t bA = *(const uint16_t*)(BN + (uint32_t)(m0 + g) * BP + col);
            uint16_t bB = *(const uint16_t*)(BN + (uint32_t)(m0 + g + 8) * BP + col);
            float p0 = fast_exp2(sc[j][0] + zt[bA & 0xFF]);
            float p1 = fast_exp2(sc[j][1] + zt[bA >> 8]);
            float p2 = fast_exp2(sc[j][2] + zt[bB & 0xFF]);
            float p3 = fast_exp2(sc[j][3] + zt[bB >> 8]);
            l0 += p0 + p1;
            l1 += p2 + p3;
            int kp = j >> 1, hf = (j & 1) * 2;
            ph[kp][hf + 0] = pack2h(p0, p1);
            ph[kp][hf + 1] = pack2h(p2, p3);
        }

        // ---- O += P V (ldmatrix.trans fragments) ----
        #pragma unroll
        for (int kp = 0; kp < 8; kp++) {
            #pragma unroll
            for (int jjp = 0; jjp < 2; jjp++) {
                uint32_t v0, v1, v2, v3;
                ldsm4t(v0, v1, v2, v3,
                       sb + VT_O + vln + (uint32_t)kp * (16 * VP) + jjp * 32);
                mma_fp16(oc[4 * jjp + 0], ph[kp], v0, v1);
                mma_fp16(oc[4 * jjp + 1], ph[kp], v2, v3);
            }
            #pragma unroll
            for (int jjp = 0; jjp < 2; jjp++) {
                uint32_t v0, v1, v2, v3;
                ldsm4t(v0, v1, v2, v3,
                       sb + VT_O + vln + (uint32_t)kp * (16 * VP) + 64 + jjp * 32);
                mma_fp16(oc[4 * jjp + 2], ph[kp], v0, v1);
                mma_fp16(oc[4 * jjp + 3], ph[kp], v2, v3);
            }
        }
        __syncthreads();
    }

    // ---- cross-quad l reduction, normalize, store split-fp16 AO ----
    l0 += __shfl_xor_sync(0xffffffffu, l0, 1);
    l0 += __shfl_xor_sync(0xffffffffu, l0, 2);
    l1 += __shfl_xor_sync(0xffffffffu, l1, 1);
    l1 += __shfl_xor_sync(0xffffffffu, l1, 2);
    float inv0 = 1.0f / l0, inv1 = 1.0f / l1;

    int r0 = q0 + m0 + g, r1 = r0 + 8;
    #pragma unroll
    for (int jj = 0; jj < 8; jj++) {
        // oc index -> d column: jj in {0,1,4,5} from first group... recover mapping:
        // oc[4*jjp + q] covers d = 8*(2*q4sel)... simpler: oc[j2] covers:
        // group A (kp loop, first ldsm4t pair): oc[0]=d0-8, oc[1]=d8-16, oc[4]=d16-24? No:
        // jjp=0: oc[0]=d[0,8), oc[1]=d[8,16); jjp=1: oc[4]=d[16? ...
        // Mapping defined below matches the loads: see col computation.
        int dcol;
        if (jj == 0) dcol = 0;
        else if (jj == 1) dcol = 8;
        else if (jj == 4) dcol = 16;
        else if (jj == 5) dcol = 24;
        else if (jj == 2) dcol = 32;
        else if (jj == 3) dcol = 40;
        else if (jj == 6) dcol = 48;
        else dcol = 56;
        int col = h * HDIM + dcol + 2 * t;
        float v00 = oc[jj][0] * inv0, v01 = oc[jj][1] * inv0;
        float v10 = oc[jj][2] * inv1, v11 = oc[jj][3] * inv1;
        __half h00 = __float2half_rn(v00);
        __half h01 = __float2half_rn(v01);
        __half h10 = __float2half_rn(v10);
        __half h11 = __float2half_rn(v11);
        __half2 u0; u0.x = h00; u0.y = h01;
        __half2 u1; u1.x = h10; u1.y = h11;
        *(uint32_t*)&g_AOh[(size_t)r0 * DMOD + col] = *(uint32_t*)&u0;
        *(uint32_t*)&g_AOh[(size_t)r1 * DMOD + col] = *(uint32_t*)&u1;
        *(uint32_t*)&g_AOl[(size_t)r0 * DMOD + col] =
            pack2h(v00 - __half2float(h00), v01 - __half2float(h01));
        *(uint32_t*)&g_AOl[(size_t)r1 * DMOD + col] =
            pack2h(v10 - __half2float(h10), v11 - __half2float(h11));
    }
}

// ---------------------------------------------------------------------------

extern "C" void kernel_launch(void* const* d_in, const int* in_sizes, int n_in,
                              void* d_out, int out_size)
{
    const float* x  = (const float*)d_in[0];
    const float* z  = (const float*)d_in[1];
    const float* Wq = (const float*)d_in[2];
    const float* bq = (const float*)d_in[3];
    const float* Wk = (const float*)d_in[4];
    const float* bk = (const float*)d_in[5];
    const float* Wv = (const float*)d_in[6];
    const float* bv = (const float*)d_in[7];
    const float* Wo = (const float*)d_in[8];
    const float* bo = (const float*)d_in[9];
    const float* zt = (const float*)d_in[10];
    float* out = (float*)d_out;

    cudaFuncSetAttribute(attn_mma_kernel,
                         cudaFuncAttributeMaxDynamicSharedMemorySize, ATTN_SMEM);
    cudaFuncSetAttribute(gemm_mma_kernel,
                         cudaFuncAttributeMaxDynamicSharedMemorySize, GEMM_SMEM);

    // fused prep: bins + W transpose (fp16) + x split (fp16)
    prep_in_kernel<<<9216, 256>>>(x, z, Wq, Wk, Wv, Wo);

    // fused QKV projection (2-term fp16); epilogue emits Qf/Kf/Vf fp16
    gemm_mma_kernel<<<dim3(12, 16), 256, GEMM_SMEM>>>(0, bq, bk, bv, nullptr);

    // attention (V via ldmatrix.trans — no transpose kernel)
    attn_mma_kernel<<<dim3(NTOK / 128, NH), 256, ATTN_SMEM>>>(zt);

    // output projection (2-term fp16)
    gemm_mma_kernel<<<dim3(4, 16), 256, GEMM_SMEM>>>(1, bo, nullptr, nullptr, out);
}

// round 13
// speedup vs baseline: 1.3731x; 1.1166x over previous
#include <cuda_runtime.h>
#include <cuda_fp16.h>
#include <math.h>
#include <stdint.h>

#define NTOK 2048
#define DMOD 512
#define NH 8
#define HDIM 64
#define NBINS 16

// ---------------------------------------------------------------------------
// Scratch (no cudaMalloc). Only referenced from DEVICE code.
// ---------------------------------------------------------------------------
__device__ __half g_Xh[NTOK * DMOD], g_Xl[NTOK * DMOD];    // split x (fp16 hi/lo)
__device__ __half g_Wt[1536 * 512];                        // (Wq|Wk|Wv)^T fp16
__device__ __half g_Wot[512 * 512];                        // Wo^T fp16
__device__ __half g_AOh[NTOK * DMOD], g_AOl[NTOK * DMOD];  // attn out split fp16
__device__ __half g_Qf[NTOK * DMOD];                       // [h][tok][64] fp16
__device__ __half g_Kf[NTOK * DMOD];                       // [h][tok][64] fp16
__device__ __half g_Vf[NTOK * DMOD];                       // [h][tok][64] fp16
__device__ uint8_t g_bins[NTOK * NTOK];

#define LOG2E 1.4426950408889634f

// ---------------------------------------------------------------------------
// mma.sync / cp.async / ldmatrix helpers
// ---------------------------------------------------------------------------
__device__ __forceinline__ void mma_fp16(float* c, const uint32_t* a,
                                         uint32_t b0, uint32_t b1) {
    asm volatile(
        "mma.sync.aligned.m16n8k16.row.col.f32.f16.f16.f32 "
        "{%0,%1,%2,%3},{%4,%5,%6,%7},{%8,%9},{%0,%1,%2,%3};"
        : "+f"(c[0]), "+f"(c[1]), "+f"(c[2]), "+f"(c[3])
        : "r"(a[0]), "r"(a[1]), "r"(a[2]), "r"(a[3]), "r"(b0), "r"(b1));
}
__device__ __forceinline__ void ldsm4(uint32_t& r0, uint32_t& r1,
                                      uint32_t& r2, uint32_t& r3, uint32_t addr) {
    asm volatile("ldmatrix.sync.aligned.m8n8.x4.shared.b16 {%0,%1,%2,%3}, [%4];"
                 : "=r"(r0), "=r"(r1), "=r"(r2), "=r"(r3) : "r"(addr));
}
__device__ __forceinline__ void ldsm4t(uint32_t& r0, uint32_t& r1,
                                       uint32_t& r2, uint32_t& r3, uint32_t addr) {
    asm volatile("ldmatrix.sync.aligned.m8n8.x4.trans.shared.b16 {%0,%1,%2,%3}, [%4];"
                 : "=r"(r0), "=r"(r1), "=r"(r2), "=r"(r3) : "r"(addr));
}
__device__ __forceinline__ void cp16(uint32_t dst, const void* src) {
    asm volatile("cp.async.cg.shared.global [%0], [%1], 16;" :: "r"(dst), "l"(src));
}
__device__ __forceinline__ uint32_t smem_u32(const void* p) {
    uint32_t a;
    asm("{ .reg .u64 t; cvta.to.shared.u64 t, %1; cvt.u32.u64 %0, t; }"
        : "=r"(a) : "l"(p));
    return a;
}
__device__ __forceinline__ uint32_t pack2h(float a, float b) {
    __half2 t;
    t.x = __float2half_rn(a);
    t.y = __float2half_rn(b);
    return *(uint32_t*)&t;
}
__device__ __forceinline__ float fast_exp2(float x) {
    float r;
    asm("ex2.approx.ftz.f32 %0, %1;" : "=f"(r) : "f"(x));
    return r;
}

// ---------------------------------------------------------------------------
// 2-term split-fp16 tensor-core GEMM, 64x128 (MxN) tiles for occupancy.
// 8 warps = 4 M-groups x 2 N-halves. mode 0: QKV (grid 12x32=384 CTAs);
// mode 1: outproj (grid 4x32=128 CTAs).
// ---------------------------------------------------------------------------
#define GPIT 80
#define GAH 0
#define GAL 5120
#define GB  10240
#define GSTAGE 20480
#define GEMM_SMEM (2 * GSTAGE)

__global__ __launch_bounds__(256, 2) void gemm_mma_kernel(
    int mode, const float* __restrict__ b0p, const float* __restrict__ b1p,
    const float* __restrict__ b2p, float* __restrict__ C_ext)
{
    extern __shared__ char smem[];
    const __half *Ah, *Al, *Bt;
    if (mode == 0) {
        Ah = g_Xh;  Al = g_Xl;  Bt = g_Wt;
    } else {
        Ah = g_AOh; Al = g_AOl; Bt = g_Wot;
    }

    const int tid = threadIdx.x;
    const int w = tid >> 5, l = tid & 31, g = l >> 2, t = l & 3;
    const int q4 = l >> 3, r8 = l & 7;
    const int wq = w & 3;          // M row-group
    const int wn = w >> 2;         // N half (64 cols)
    const int n0 = blockIdx.x * 128;
    const int mb = blockIdx.y * 64;
    const uint32_t sbase = smem_u32(smem);

    const uint32_t aln = (uint32_t)(wq * 16 + 8 * (q4 & 1) + r8) * GPIT + 16 * (q4 >> 1);
    const uint32_t bln = (uint32_t)(wn * 64 + 8 * (q4 >> 1) + r8) * GPIT + 16 * (q4 & 1);

    auto load = [&](int kc, int st) {
        uint32_t b = sbase + st * GSTAGE;
        {   // A hi/lo: 64 rows x 64B
            int r = tid >> 2, c = tid & 3;
            uint32_t so = r * GPIT + c * 16;
            size_t ga = ((size_t)(mb + r) * 512 + kc * 32) * 2 + c * 16;
            cp16(b + GAH + so, (const char*)Ah + ga);
            cp16(b + GAL + so, (const char*)Al + ga);
        }
        #pragma unroll
        for (int p = 0; p < 2; p++) {   // B: 128 rows x 64B
            int i = tid + p * 256;
            int r = i >> 2, c = i & 3;
            size_t gb = ((size_t)(n0 + r) * 512 + kc * 32) * 2 + c * 16;
            cp16(b + GB + r * GPIT + c * 16, (const char*)Bt + gb);
        }
        asm volatile("cp.async.commit_group;" ::: "memory");
    };

    float acc[8][4];
    #pragma unroll
    for (int j = 0; j < 8; j++)
        #pragma unroll
        for (int i = 0; i < 4; i++) acc[j][i] = 0.0f;

    load(0, 0);
    for (int kc = 0; kc < 16; kc++) {
        if (kc + 1 < 16) {
            load(kc + 1, (kc + 1) & 1);
            asm volatile("cp.async.wait_group 1;" ::: "memory");
        } else {
            asm volatile("cp.async.wait_group 0;" ::: "memory");
        }
        __syncthreads();
        const uint32_t sb = sbase + (kc & 1) * GSTAGE;

        #pragma unroll
        for (int kk = 0; kk < 2; kk++) {
            uint32_t ah[4], al[4];
            ldsm4(ah[0], ah[1], ah[2], ah[3], sb + GAH + aln + kk * 32);
            ldsm4(al[0], al[1], al[2], al[3], sb + GAL + aln + kk * 32);
            #pragma unroll
            for (int jp = 0; jp < 4; jp++) {
                uint32_t b0, b1, b2, b3;
                ldsm4(b0, b1, b2, b3, sb + GB + bln + (uint32_t)jp * (16 * GPIT) + kk * 32);
                mma_fp16(acc[2 * jp],     ah, b0, b1);
                mma_fp16(acc[2 * jp],     al, b0, b1);
                mma_fp16(acc[2 * jp + 1], ah, b2, b3);
                mma_fp16(acc[2 * jp + 1], al, b2, b3);
            }
        }
        __syncthreads();
    }

    const int r0 = mb + wq * 16 + g, r1 = r0 + 8;
    if (mode == 1) {
        #pragma unroll
        for (int j = 0; j < 8; j++) {
            int col = n0 + wn * 64 + 8 * j + 2 * t;
            float bv0 = b0p[col], bv1 = b0p[col + 1];
            *(float2*)&C_ext[(size_t)r0 * 512 + col] =
                make_float2(acc[j][0] + bv0, acc[j][1] + bv1);
            *(float2*)&C_ext[(size_t)r1 * 512 + col] =
                make_float2(acc[j][2] + bv0, acc[j][3] + bv1);
        }
    } else {
        const float QS = 0.125f * LOG2E;
        #pragma unroll
        for (int j = 0; j < 8; j++) {
            int col = n0 + wn * 64 + 8 * j + 2 * t;
            const float* bp = (col < 512) ? b0p : (col < 1024 ? b1p : b2p);
            int cc = col & 511;
            float bv0 = bp[cc], bv1 = bp[cc + 1];
            float v00 = acc[j][0] + bv0, v01 = acc[j][1] + bv1;
            float v10 = acc[j][2] + bv0, v11 = acc[j][3] + bv1;
            int h = cc >> 6, d = cc & 63;
            size_t d0 = ((size_t)h * NTOK + r0) * HDIM + d;
            size_t d1 = ((size_t)h * NTOK + r1) * HDIM + d;
            if (col < 512) {
                *(uint32_t*)&g_Qf[d0] = pack2h(v00 * QS, v01 * QS);
                *(uint32_t*)&g_Qf[d1] = pack2h(v10 * QS, v11 * QS);
            } else if (col < 1024) {
                *(uint32_t*)&g_Kf[d0] = pack2h(v00, v01);
                *(uint32_t*)&g_Kf[d1] = pack2h(v10, v11);
            } else {
                *(uint32_t*)&g_Vf[d0] = pack2h(v00, v01);
                *(uint32_t*)&g_Vf[d1] = pack2h(v10, v11);
            }
        }
    }
}

// ---------------------------------------------------------------------------
// Fused input prep:
//   blocks [0,4096): z bins | [4096,5120): W transpose (fp16) | [5120,9216): x split fp16
// ---------------------------------------------------------------------------
__device__ __forceinline__ uint8_t bin_of(float z) {
    int b = (int)floorf(z / 5.0f * 16.0f);
    return (uint8_t)max(0, min(NBINS - 1, b));
}

__global__ __launch_bounds__(256) void prep_in_kernel(
    const float* __restrict__ x, const float* __restrict__ zmat,
    const float* __restrict__ Wq, const float* __restrict__ Wk,
    const float* __restrict__ Wv, const float* __restrict__ Wo)
{
    int bx = blockIdx.x;
    int tid = threadIdx.x;
    if (bx < 4096) {
        size_t i = (size_t)bx * 256 + tid;
        float4 z = *(const float4*)(zmat + i * 4);
        uchar4 b;
        b.x = bin_of(z.x); b.y = bin_of(z.y); b.z = bin_of(z.z); b.w = bin_of(z.w);
        *(uchar4*)(g_bins + i * 4) = b;
    } else if (bx < 5120) {
        __shared__ float ts[32][33];
        int bb = bx - 4096;
        int zb = bb >> 8, rem = bb & 255;
        int k0 = (rem & 15) * 32;
        int n0 = (rem >> 4) * 32;
        const float* src;
        __half* dh;
        int nbase;
        if (zb == 0)      { src = Wq; dh = g_Wt;  nbase = 0; }
        else if (zb == 1) { src = Wk; dh = g_Wt;  nbase = 512; }
        else if (zb == 2) { src = Wv; dh = g_Wt;  nbase = 1024; }
        else              { src = Wo; dh = g_Wot; nbase = 0; }
        int tx = tid & 31, ty = tid >> 5;
        #pragma unroll
        for (int i = 0; i < 4; i++) {
            int r = ty + i * 8;
            ts[r][tx] = src[(size_t)(k0 + r) * 512 + n0 + tx];
        }
        __syncthreads();
        #pragma unroll
        for (int i = 0; i < 4; i++) {
            int nn = ty + i * 8;
            dh[(size_t)(nbase + n0 + nn) * 512 + k0 + tx] = __float2half_rn(ts[tx][nn]);
        }
    } else {
        int i = (bx - 5120) * 256 + tid;
        float v = x[i];
        __half h = __float2half_rn(v);
        g_Xh[i] = h;
        g_Xl[i] = __float2half_rn(v - __half2float(h));
    }
}

// ---------------------------------------------------------------------------
// fp16 mma.sync flash attention (validated R12): 128 q-rows, 8 warps.
// K via ldmatrix; V via ldmatrix.trans from [tok][64] tiles.
// l accumulated as fp32 FADDs in the exp loop.
// ---------------------------------------------------------------------------
#define KP 144
#define VP 144
#define BP 144
#define KF_O 0
#define VT_O 18432
#define BN_O 36864
#define STAGE 55296
#define ATTN_SMEM (2 * STAGE)

__global__ __launch_bounds__(256, 1) void attn_mma_kernel(const float* __restrict__ ztab)
{
    extern __shared__ char smem[];
    __shared__ float zt[NBINS];

    const int tid = threadIdx.x;
    const int w   = tid >> 5;
    const int l   = tid & 31;
    const int g   = l >> 2;
    const int t   = l & 3;
    const int q4  = l >> 3, r8 = l & 7;
    const int h   = blockIdx.y;
    const int q0  = blockIdx.x * 128;
    const int m0  = w * 16;

    if (tid < NBINS) zt[tid] = ztab[tid * NH + h] * LOG2E;

    const uint32_t sbase = smem_u32(smem);

    const uint32_t kln = (uint32_t)(8 * (q4 >> 1) + r8) * KP + 16 * (q4 & 1);
    const uint32_t vln = (uint32_t)(8 * (q4 & 1) + r8) * VP + 16 * (q4 >> 1);

    auto load_tile = [&](int kt, int stage) {
        uint32_t base = sbase + stage * STAGE;
        #pragma unroll
        for (int p = 0; p < 4; p++) {
            int i = tid + p * 256;
            int r = i >> 3, c = i & 7;
            cp16(base + KF_O + r * KP + c * 16,
                 (const char*)g_Kf + (((size_t)h * NTOK + kt * 128 + r) * HDIM) * 2 + c * 16);
        }
        #pragma unroll
        for (int p = 0; p < 4; p++) {
            int i = tid + p * 256;
            int r = i >> 3, c = i & 7;
            cp16(base + VT_O + r * VP + c * 16,
                 (const char*)g_Vf + (((size_t)h * NTOK + kt * 128 + r) * HDIM) * 2 + c * 16);
        }
        #pragma unroll
        for (int p = 0; p < 4; p++) {
            int i = tid + p * 256;
            int r = i >> 3, c = i & 7;
            cp16(base + BN_O + r * BP + c * 16,
                 g_bins + (size_t)(q0 + r) * NTOK + kt * 128 + c * 16);
        }
        asm volatile("cp.async.commit_group;" ::: "memory");
    };

    load_tile(0, 0);

    uint32_t qf[4][4];
    {
        const uint16_t* qb = (const uint16_t*)g_Qf + ((size_t)h * NTOK + q0 + m0) * HDIM;
        #pragma unroll
        for (int kk = 0; kk < 4; kk++) {
            int c0 = 16 * kk + 2 * t;
            qf[kk][0] = *(const uint32_t*)(qb + (size_t)g * HDIM + c0);
            qf[kk][1] = *(const uint32_t*)(qb + (size_t)(g + 8) * HDIM + c0);
            qf[kk][2] = *(const uint32_t*)(qb + (size_t)g * HDIM + c0 + 8);
            qf[kk][3] = *(const uint32_t*)(qb + (size_t)(g + 8) * HDIM + c0 + 8);
        }
    }

    float oc[8][4];
    #pragma unroll
    for (int j = 0; j < 8; j++)
        #pragma unroll
        for (int i = 0; i < 4; i++) oc[j][i] = 0.0f;
    float l0 = 0.0f, l1 = 0.0f;

    for (int kt = 0; kt < NTOK / 128; kt++) {
        if (kt + 1 < NTOK / 128) {
            load_tile(kt + 1, (kt + 1) & 1);
            asm volatile("cp.async.wait_group 1;" ::: "memory");
        } else {
            asm volatile("cp.async.wait_group 0;" ::: "memory");
        }
        __syncthreads();

        const uint32_t sb = sbase + (kt & 1) * STAGE;
        const char* BN = smem + (kt & 1) * STAGE + BN_O;

        float sc[16][4];
        #pragma unroll
        for (int j = 0; j < 16; j++)
            #pragma unroll
            for (int i = 0; i < 4; i++) sc[j][i] = 0.0f;

        #pragma unroll
        for (int kk = 0; kk < 4; kk++) {
            #pragma unroll
            for (int jp = 0; jp < 8; jp++) {
                uint32_t b0, b1, b2, b3;
                ldsm4(b0, b1, b2, b3, sb + KF_O + kln + (uint32_t)jp * (16 * KP) + kk * 32);
                mma_fp16(sc[2 * jp],     qf[kk], b0, b1);
                mma_fp16(sc[2 * jp + 1], qf[kk], b2, b3);
            }
        }

        uint32_t ph[8][4];
        #pragma unroll
        for (int j = 0; j < 16; j++) {
            int col = 8 * j + 2 * t;
            uint16_t bA = *(const uint16_t*)(BN + (uint32_t)(m0 + g) * BP + col);
            uint16_t bB = *(const uint16_t*)(BN + (uint32_t)(m0 + g + 8) * BP + col);
            float p0 = fast_exp2(sc[j][0] + zt[bA & 0xFF]);
            float p1 = fast_exp2(sc[j][1] + zt[bA >> 8]);
            float p2 = fast_exp2(sc[j][2] + zt[bB & 0xFF]);
            float p3 = fast_exp2(sc[j][3] + zt[bB >> 8]);
            l0 += p0 + p1;
            l1 += p2 + p3;
            int kp = j >> 1, hf = (j & 1) * 2;
            ph[kp][hf + 0] = pack2h(p0, p1);
            ph[kp][hf + 1] = pack2h(p2, p3);
        }

        #pragma unroll
        for (int kp = 0; kp < 8; kp++) {
            #pragma unroll
            for (int jjp = 0; jjp < 2; jjp++) {
                uint32_t v0, v1, v2, v3;
                ldsm4t(v0, v1, v2, v3,
                       sb + VT_O + vln + (uint32_t)kp * (16 * VP) + jjp * 32);
                mma_fp16(oc[4 * jjp + 0], ph[kp], v0, v1);
                mma_fp16(oc[4 * jjp + 1], ph[kp], v2, v3);
            }
            #pragma unroll
            for (int jjp = 0; jjp < 2; jjp++) {
                uint32_t v0, v1, v2, v3;
                ldsm4t(v0, v1, v2, v3,
                       sb + VT_O + vln + (uint32_t)kp * (16 * VP) + 64 + jjp * 32);
                mma_fp16(oc[4 * jjp + 2], ph[kp], v0, v1);
                mma_fp16(oc[4 * jjp + 3], ph[kp], v2, v3);
            }
        }
        __syncthreads();
    }

    l0 += __shfl_xor_sync(0xffffffffu, l0, 1);
    l0 += __shfl_xor_sync(0xffffffffu, l0, 2);
    l1 += __shfl_xor_sync(0xffffffffu, l1, 1);
    l1 += __shfl_xor_sync(0xffffffffu, l1, 2);
    float inv0 = 1.0f / l0, inv1 = 1.0f / l1;

    // oc index -> head-dim column base (from the two ldsm4t groups above)
    const int dmap[8] = {0, 8, 32, 40, 16, 24, 48, 56};

    int r0 = q0 + m0 + g, r1 = r0 + 8;
    #pragma unroll
    for (int jj = 0; jj < 8; jj++) {
        int col = h * HDIM + dmap[jj] + 2 * t;
        float v00 = oc[jj][0] * inv0, v01 = oc[jj][1] * inv0;
        float v10 = oc[jj][2] * inv1, v11 = oc[jj][3] * inv1;
        __half h00 = __float2half_rn(v00);
        __half h01 = __float2half_rn(v01);
        __half h10 = __float2half_rn(v10);
        __half h11 = __float2half_rn(v11);
        __half2 u0; u0.x = h00; u0.y = h01;
        __half2 u1; u1.x = h10; u1.y = h11;
        *(uint32_t*)&g_AOh[(size_t)r0 * DMOD + col] = *(uint32_t*)&u0;
        *(uint32_t*)&g_AOh[(size_t)r1 * DMOD + col] = *(uint32_t*)&u1;
        *(uint32_t*)&g_AOl[(size_t)r0 * DMOD + col] =
            pack2h(v00 - __half2float(h00), v01 - __half2float(h01));
        *(uint32_t*)&g_AOl[(size_t)r1 * DMOD + col] =
            pack2h(v10 - __half2float(h10), v11 - __half2float(h11));
    }
}

// ---------------------------------------------------------------------------

extern "C" void kernel_launch(void* const* d_in, const int* in_sizes, int n_in,
                              void* d_out, int out_size)
{
    const float* x  = (const float*)d_in[0];
    const float* z  = (const float*)d_in[1];
    const float* Wq = (const float*)d_in[2];
    const float* bq = (const float*)d_in[3];
    const float* Wk = (const float*)d_in[4];
    const float* bk = (const float*)d_in[5];
    const float* Wv = (const float*)d_in[6];
    const float* bv = (const float*)d_in[7];
    const float* Wo = (const float*)d_in[8];
    const float* bo = (const float*)d_in[9];
    const float* zt = (const float*)d_in[10];
    float* out = (float*)d_out;

    cudaFuncSetAttribute(attn_mma_kernel,
                         cudaFuncAttributeMaxDynamicSharedMemorySize, ATTN_SMEM);
    cudaFuncSetAttribute(gemm_mma_kernel,
                         cudaFuncAttributeMaxDynamicSharedMemorySize, GEMM_SMEM);

    // fused prep: bins + W transpose (fp16) + x split (fp16)
    prep_in_kernel<<<9216, 256>>>(x, z, Wq, Wk, Wv, Wo);

    // fused QKV projection (2-term fp16, 64x128 tiles -> 384 CTAs)
    gemm_mma_kernel<<<dim3(12, 32), 256, GEMM_SMEM>>>(0, bq, bk, bv, nullptr);

    // attention (V via ldmatrix.trans)
    attn_mma_kernel<<<dim3(NTOK / 128, NH), 256, ATTN_SMEM>>>(zt);

    // output projection (64x128 tiles -> 128 CTAs)
    gemm_mma_kernel<<<dim3(4, 32), 256, GEMM_SMEM>>>(1, bo, nullptr, nullptr, out);
}